// round 17
// baseline (speedup 1.0000x reference)
#include <cuda_runtime.h>
#include <cuda_bf16.h>
#include <math.h>
#include <cstdint>

#define BB 16
#define CC 192
#define HALF 96
#define TLEN 2048
#define FF 256
#define NB 10
#define NJ 29        // 3*NB - 1

// ---- proj mma tiling (1-term, 4x64-k pipelined) ----
#define MROWS 3072   // 96 ch * 32 padded rows
#define MT 128       // m-tile (4 channels)
#define NT 128       // t-tile
#define PSTR 144     // smem row stride bytes (64 bf16 + 16B pad)
#define USTRIDE 129  // u smem row stride (floats)

#define PROJ_STG 36864        // per-slot: A 128*144 + B 128*144
#define OFF_MASK 73728        // 128 floats
#define OFF_RED  74240        // 8 floats
#define PROJ_SMEM_BYTES 74368

// ---- fused layer (conv+norm+gelu + pw mma + norm+gelu+residual) ----
#define YSTR 528              // 256 bf16 + 16B pad
#define FPW_OFF_A   0         // 256*528 = 135168 (full pw weight tile)
#define FPW_OFF_Y   135168    // 128*528 = 67584 (y tile, bf16)
#define FPW_OFF_CW  202752    // conv params: 1536 floats = 6144 B
#define FPW_OFF_STAT 208896   // smean[64] | srstd[64] = 512 B
#define FPW_SMEM_BYTES 209408
#define PW_USTR 260           // epilogue f32 row stride (words)

// ---- pre mma tiling (M=256 f, N=128 t, K=96 whole) ----
#define PRE_STR 208
#define PRE_OFF_AHI 0
#define PRE_OFF_ALO 53248
#define PRE_OFF_BHI 106496
#define PRE_OFF_BLO 133120
#define PRE_SMEM_BYTES 159744

// Scratch (allocation-free rule: __device__ globals). Layout: [b][t][f].
__device__ float g_hA[(size_t)BB*TLEN*FF];
__device__ float g_hB[(size_t)BB*TLEN*FF];
__device__ __nv_bfloat16 g_whi[(size_t)MROWS*FF];
__device__ __nv_bfloat16 g_hhi[(size_t)BB*TLEN*FF];
__device__ __nv_bfloat16 g_pwhi[(size_t)3*FF*FF];
__device__ __nv_bfloat16 g_prehi[(size_t)FF*HALF];
__device__ __nv_bfloat16 g_prelo[(size_t)FF*HALF];

__device__ __forceinline__ float gelu_exact(float v){
    return 0.5f * v * (1.f + erff(v * 0.70710678118654752f));
}
__device__ __forceinline__ float softplus_fast(float v){
    return v > 20.f ? v : __logf(1.f + __expf(v));
}
__device__ __forceinline__ uint32_t smem_u32(const void* p){
    uint32_t a;
    asm("{ .reg .u64 t; cvta.to.shared.u64 t, %1; cvt.u32.u64 %0, t; }" : "=r"(a) : "l"(p));
    return a;
}
__device__ __forceinline__ void ldm4(uint32_t* r, uint32_t addr){
    asm volatile("ldmatrix.sync.aligned.m8n8.x4.shared.b16 {%0,%1,%2,%3}, [%4];"
        : "=r"(r[0]),"=r"(r[1]),"=r"(r[2]),"=r"(r[3]) : "r"(addr));
}
__device__ __forceinline__ void mma_bf16(float* d, const uint32_t* a, uint32_t b0, uint32_t b1){
    asm volatile("mma.sync.aligned.m16n8k16.row.col.f32.bf16.bf16.f32 "
        "{%0,%1,%2,%3}, {%4,%5,%6,%7}, {%8,%9}, {%0,%1,%2,%3};"
        : "+f"(d[0]),"+f"(d[1]),"+f"(d[2]),"+f"(d[3])
        : "r"(a[0]),"r"(a[1]),"r"(a[2]),"r"(a[3]), "r"(b0),"r"(b1));
}
__device__ __forceinline__ void cp16(uint32_t saddr, const void* gptr){
    asm volatile("cp.async.cg.shared.global [%0], [%1], 16;"
        :: "r"(saddr), "l"(gptr));
}
__device__ __forceinline__ void cp_commit(){
    asm volatile("cp.async.commit_group;");
}
__device__ __forceinline__ void cp_waitg1(){
    asm volatile("cp.async.wait_group 1;" ::: "memory");
}
__device__ __forceinline__ void cp_waitg0(){
    asm volatile("cp.async.wait_group 0;" ::: "memory");
}
__device__ __forceinline__ void cp_wait_all(){
    asm volatile("cp.async.commit_group;");
    asm volatile("cp.async.wait_all;" ::: "memory");
}

// ---------------------------------------------------------------------------
// Merged prep: proj_w (padded) | pw_w | pre_w hi/lo, one launch.
// ---------------------------------------------------------------------------
#define NPROJ ((long)MROWS*FF)
#define NPW   (3L*FF*FF)
#define NPRE  ((long)FF*HALF)
__global__ void k_prep_all(const float* __restrict__ proj_w,
                           const float* __restrict__ pw_w,
                           const float* __restrict__ pre_w){
    long n = NPROJ + NPW + NPRE;
    for (long i = (long)blockIdx.x*blockDim.x + threadIdx.x; i < n;
         i += (long)gridDim.x*blockDim.x){
        if (i < NPROJ){
            int k = (int)(i & (FF-1));
            int r = (int)(i >> 8);
            int ch = r >> 5, j = r & 31;
            float w = (j < NJ) ? proj_w[((long)(ch*NJ + j))*FF + k] : 0.f;
            g_whi[i] = __float2bfloat16_rn(w);
        } else if (i < NPROJ + NPW){
            long j = i - NPROJ;
            g_pwhi[j] = __float2bfloat16_rn(pw_w[j]);
        } else {
            long j = i - NPROJ - NPW;
            float w = pre_w[j];
            __nv_bfloat16 hi = __float2bfloat16_rn(w);
            g_prehi[j] = hi;
            g_prelo[j] = __float2bfloat16_rn(w - __bfloat162float(hi));
        }
    }
}

// ---------------------------------------------------------------------------
// Kernel 0: copy x0*mask into out[:, :96, :] (float4), zero logdet.
// ---------------------------------------------------------------------------
__global__ __launch_bounds__(256) void k_init(const float* __restrict__ x,
                                              const float* __restrict__ mask,
                                              float* __restrict__ out){
    int t4 = blockIdx.x * 256 + threadIdx.x;
    int c = blockIdx.y, b = blockIdx.z;
    long row = (long)b*CC*TLEN + (long)c*TLEN;
    float4 v = *(const float4*)&x[row + t4*4];
    const float4 m = *(const float4*)&mask[(long)b*TLEN + t4*4];
    v.x *= m.x; v.y *= m.y; v.z *= m.z; v.w *= m.w;
    *(float4*)&out[row + t4*4] = v;
    if (blockIdx.x == 0 && blockIdx.y == 0 && threadIdx.x == 0)
        out[(long)BB*CC*TLEN + b] = 0.f;
}

// ---------------------------------------------------------------------------
// Kernel 1: h = pre_w @ x0 + pre_b via ldmatrix+mma (bf16 3-term) -> g_hA.
// ---------------------------------------------------------------------------
__global__ __launch_bounds__(512) void k_pre_mma(const float* __restrict__ x,
                                                 const float* __restrict__ pre_b){
    extern __shared__ char smem[];
    uint32_t sb = smem_u32(smem);
    int tid = threadIdx.x, lane = tid & 31, wid = tid >> 5;
    int t0 = blockIdx.x * 128;
    int b = blockIdx.y;

    for (int i = tid; i < FF*12; i += 512){
        int r = i / 12, g = i - r*12;
        uint32_t off = (uint32_t)(r*PRE_STR + g*16);
        cp16(sb + PRE_OFF_AHI + off, ((const uint4*)g_prehi) + (size_t)r*12 + g);
        cp16(sb + PRE_OFF_ALO + off, ((const uint4*)g_prelo) + (size_t)r*12 + g);
    }
    for (int i = tid; i < HALF*128; i += 512){
        int c = i >> 7, tt = i & 127;
        float v = x[(long)b*CC*TLEN + (long)c*TLEN + t0 + tt];
        __nv_bfloat16 hi = __float2bfloat16_rn(v);
        uint32_t off = (uint32_t)(tt*PRE_STR + c*2);
        *(__nv_bfloat16*)(smem + PRE_OFF_BHI + off) = hi;
        *(__nv_bfloat16*)(smem + PRE_OFF_BLO + off) =
            __float2bfloat16_rn(v - __bfloat162float(hi));
    }
    cp_wait_all();
    __syncthreads();

    int wm = wid & 7, wn = wid >> 3;
    float acc[2][8][4];
    #pragma unroll
    for (int mt = 0; mt < 2; mt++)
        #pragma unroll
        for (int nt = 0; nt < 8; nt++)
            #pragma unroll
            for (int q = 0; q < 4; q++) acc[mt][nt][q] = 0.f;

    uint32_t aoff = (uint32_t)((wm*32 + (lane & 15)) * PRE_STR + ((lane >> 4) * 8) * 2);
    uint32_t aH0 = sb + PRE_OFF_AHI + aoff, aH1 = aH0 + 16*PRE_STR;
    uint32_t aL0 = sb + PRE_OFF_ALO + aoff, aL1 = aL0 + 16*PRE_STR;
    uint32_t boffc = (uint32_t)((((lane >> 4) * 8) + (lane & 7)) * PRE_STR
                                + ((lane >> 3) & 1) * 16);
    uint32_t bHp[2], bLp[2];
    #pragma unroll
    for (int hf = 0; hf < 2; hf++){
        uint32_t rowo = (uint32_t)((wn*64 + hf*32) * PRE_STR);
        bHp[hf] = sb + PRE_OFF_BHI + rowo + boffc;
        bLp[hf] = sb + PRE_OFF_BLO + rowo + boffc;
    }

    #pragma unroll
    for (int k16 = 0; k16 < 6; k16++){
        uint32_t ko = (uint32_t)(k16 * 32);
        uint32_t Ah[2][4], Al[2][4];
        ldm4(Ah[0], aH0 + ko); ldm4(Ah[1], aH1 + ko);
        ldm4(Al[0], aL0 + ko); ldm4(Al[1], aL1 + ko);
        #pragma unroll
        for (int hf = 0; hf < 2; hf++){
            uint32_t Bh[2][4], Bl[2][4];
            ldm4(Bh[0], bHp[hf] + ko); ldm4(Bh[1], bHp[hf] + 16*PRE_STR + ko);
            ldm4(Bl[0], bLp[hf] + ko); ldm4(Bl[1], bLp[hf] + 16*PRE_STR + ko);
            #pragma unroll
            for (int mt = 0; mt < 2; mt++){
                #pragma unroll
                for (int nt = 0; nt < 4; nt++){
                    uint32_t h0 = Bh[nt>>1][(nt&1)*2], h1 = Bh[nt>>1][(nt&1)*2+1];
                    uint32_t l0 = Bl[nt>>1][(nt&1)*2], l1 = Bl[nt>>1][(nt&1)*2+1];
                    mma_bf16(acc[mt][hf*4+nt], Ah[mt], h0, h1);
                    mma_bf16(acc[mt][hf*4+nt], Ah[mt], l0, l1);
                    mma_bf16(acc[mt][hf*4+nt], Al[mt], h0, h1);
                }
            }
        }
    }

    float* us = (float*)smem;
    for (int p = 0; p < 2; p++){
        __syncthreads();
        if (wn == p){
            #pragma unroll
            for (int mt = 0; mt < 2; mt++){
                #pragma unroll
                for (int nt = 0; nt < 8; nt++){
                    int tl = nt*8 + (lane & 3)*2;
                    int m = wm*32 + mt*16 + (lane >> 2);
                    #pragma unroll
                    for (int hh = 0; hh < 2; hh++){
                        int o = m + hh*8;
                        float pb = pre_b[o];
                        us[tl*PW_USTR + o]     = acc[mt][nt][2*hh+0] + pb;
                        us[(tl+1)*PW_USTR + o] = acc[mt][nt][2*hh+1] + pb;
                    }
                }
            }
        }
        __syncthreads();
        long gbase = ((long)b*TLEN + t0 + p*64) * FF;
        for (int i = tid; i < 64*64; i += 512){
            int t = i >> 6, o4 = i & 63;
            *(float4*)&g_hA[gbase + (long)t*FF + o4*4] = *(float4*)&us[t*PW_USTR + o4*4];
        }
    }
}

// ---------------------------------------------------------------------------
// Kernel 2 (per layer, FUSED): conv+norm+gelu -> smem y tile (bf16);
// y2 = pw_w @ y via ldmatrix+mma (A fully cp.async-staged, overlapped with
// conv compute, zero mid-MMA syncs); norm+gelu+residual src->dst.
// src/dst alternate g_hA/g_hB (halo-race-free). Last layer emits g_hhi.
// ---------------------------------------------------------------------------
__global__ __launch_bounds__(512) void k_fused_layer(
        const float* __restrict__ mask,
        const float* __restrict__ dw_w,  const float* __restrict__ dw_b,
        const float* __restrict__ gamma1,const float* __restrict__ beta1,
        const float* __restrict__ pw_b,
        const float* __restrict__ gamma2,const float* __restrict__ beta2,
        int lay, int dil, int last){
    const float* src = (lay & 1) ? g_hB : g_hA;
    float*       dst = (lay & 1) ? g_hA : g_hB;

    extern __shared__ char smem[];
    uint32_t sb = smem_u32(smem);
    int tid = threadIdx.x, lane = tid & 31, wid = tid >> 5;
    int t0 = blockIdx.x * 128;
    int b = blockIdx.y;

    // 1. stage full pw weight tile via cp.async (overlaps conv phase)
    {
        const uint4* srcA = ((const uint4*)g_pwhi) + (size_t)lay*FF*32;
        for (int i = tid; i < FF*32; i += 512){
            int r = i >> 5, g = i & 31;
            cp16(sb + FPW_OFF_A + (uint32_t)(r*YSTR + g*16), srcA + (size_t)r*32 + g);
        }
        cp_commit();
    }
    // 2. conv params -> smem
    float* swt = (float*)(smem + FPW_OFF_CW);   // dw_w 768
    float* sbi = swt + 768;                      // dw_b 256
    float* sga = sbi + 256;                      // gamma1 256
    float* sbe = sga + 256;                      // beta1 256
    for (int i = tid; i < 1536; i += 512){
        float v;
        if (i < 768) v = dw_w[i];
        else if (i < 1024) v = dw_b[i-768];
        else if (i < 1280) v = gamma1[i-1024];
        else v = beta1[i-1280];
        swt[i] = v;
    }
    __syncthreads();

    // 3. conv + channel-norm + gelu -> y tile (bf16)
    {
        int tl = tid >> 2, q = tid & 3, f0 = q*64;
        int gt = t0 + tl;
        bool hasL = (gt - dil) >= 0, hasR = (gt + dil) < TLEN;
        float mc = mask[(long)b*TLEN + gt];
        float ml = hasL ? mask[(long)b*TLEN + gt - dil] : 0.f;
        float mr = hasR ? mask[(long)b*TLEN + gt + dil] : 0.f;
        long cb = ((long)b*TLEN + gt)*FF + f0;
        long lb = cb - (long)dil*FF, rb = cb + (long)dil*FF;

        float cv[64];
        float s = 0.f, sq = 0.f;
        #pragma unroll
        for (int i = 0; i < 16; i++){
            float4 c4 = *(const float4*)&src[cb + i*4];
            float4 l4 = hasL ? *(const float4*)&src[lb + i*4] : make_float4(0.f,0.f,0.f,0.f);
            float4 r4 = hasR ? *(const float4*)&src[rb + i*4] : make_float4(0.f,0.f,0.f,0.f);
            const float cc[4] = {c4.x, c4.y, c4.z, c4.w};
            const float ll[4] = {l4.x, l4.y, l4.z, l4.w};
            const float rr[4] = {r4.x, r4.y, r4.z, r4.w};
            #pragma unroll
            for (int j = 0; j < 4; j++){
                int f = f0 + i*4 + j;
                float v = fmaf(swt[f*3+0], ll[j]*ml,
                          fmaf(swt[f*3+1], cc[j]*mc,
                          fmaf(swt[f*3+2], rr[j]*mr, sbi[f])));
                cv[i*4+j] = v; s += v; sq = fmaf(v, v, sq);
            }
        }
        s  += __shfl_xor_sync(0xFFFFFFFFu, s, 1);
        s  += __shfl_xor_sync(0xFFFFFFFFu, s, 2);
        sq += __shfl_xor_sync(0xFFFFFFFFu, sq, 1);
        sq += __shfl_xor_sync(0xFFFFFFFFu, sq, 2);
        float mean = s * (1.f/FF);
        float rstd = rsqrtf(sq * (1.f/FF) - mean*mean + 1e-5f);

        uint32_t yrow = sb + FPW_OFF_Y + (uint32_t)(tl*YSTR + q*128);
        #pragma unroll
        for (int c8 = 0; c8 < 8; c8++){
            uint32_t pk[4];
            #pragma unroll
            for (int p2 = 0; p2 < 4; p2++){
                int i0 = c8*8 + p2*2;
                int f = f0 + i0;
                float y0 = gelu_exact((cv[i0]   - mean)*rstd*sga[f]   + sbe[f]);
                float y1 = gelu_exact((cv[i0+1] - mean)*rstd*sga[f+1] + sbe[f+1]);
                __nv_bfloat162 pr;
                pr.x = __float2bfloat16_rn(y0);
                pr.y = __float2bfloat16_rn(y1);
                pk[p2] = *(uint32_t*)&pr;
            }
            asm volatile("st.shared.v4.b32 [%0], {%1,%2,%3,%4};"
                :: "r"(yrow + c8*16), "r"(pk[0]), "r"(pk[1]), "r"(pk[2]), "r"(pk[3]));
        }
    }
    cp_waitg0();
    __syncthreads();

    // 4. MMA: M=256 (8 wm) x N=128 (2 wn x 2 hf x 32), K=256 in 16 k16 steps
    int wm = wid & 7, wn = wid >> 3;
    float acc[2][8][4];
    #pragma unroll
    for (int mt = 0; mt < 2; mt++)
        #pragma unroll
        for (int nt = 0; nt < 8; nt++)
            #pragma unroll
            for (int q = 0; q < 4; q++) acc[mt][nt][q] = 0.f;

    uint32_t aoff = (uint32_t)((wm*32 + (lane & 15)) * YSTR + ((lane >> 4) * 8) * 2);
    uint32_t aH0 = sb + FPW_OFF_A + aoff, aH1 = aH0 + 16*YSTR;
    uint32_t boffc = (uint32_t)((((lane >> 4) * 8) + (lane & 7)) * YSTR
                                + ((lane >> 3) & 1) * 16);
    uint32_t bB[2];
    bB[0] = sb + FPW_OFF_Y + (uint32_t)((wn*64) * YSTR) + boffc;
    bB[1] = sb + FPW_OFF_Y + (uint32_t)((wn*64 + 32) * YSTR) + boffc;

    #pragma unroll
    for (int k16 = 0; k16 < 16; k16++){
        uint32_t ko = (uint32_t)(k16 * 32);
        uint32_t Ah[2][4];
        ldm4(Ah[0], aH0 + ko); ldm4(Ah[1], aH1 + ko);
        #pragma unroll
        for (int hf = 0; hf < 2; hf++){
            uint32_t Bh[2][4];
            ldm4(Bh[0], bB[hf] + ko); ldm4(Bh[1], bB[hf] + 16*YSTR + ko);
            #pragma unroll
            for (int mt = 0; mt < 2; mt++){
                #pragma unroll
                for (int nt = 0; nt < 4; nt++){
                    uint32_t h0 = Bh[nt>>1][(nt&1)*2], h1 = Bh[nt>>1][(nt&1)*2+1];
                    mma_bf16(acc[mt][hf*4+nt], Ah[mt], h0, h1);
                }
            }
        }
    }

    // 5. epilogue in two 64-t passes (us aliases A region; A is dead)
    float* us = (float*)smem;
    float* smean = (float*)(smem + FPW_OFF_STAT);
    float* srstd = smean + 64;

    for (int p = 0; p < 2; p++){
        __syncthreads();
        if (wn == p){
            #pragma unroll
            for (int mt = 0; mt < 2; mt++){
                #pragma unroll
                for (int nt = 0; nt < 8; nt++){
                    int tl = nt*8 + (lane & 3)*2;
                    int m = wm*32 + mt*16 + (lane >> 2);
                    #pragma unroll
                    for (int hh = 0; hh < 2; hh++){
                        int o = m + hh*8;
                        float pb = pw_b[o];
                        us[tl*PW_USTR + o]     = acc[mt][nt][2*hh+0] + pb;
                        us[(tl+1)*PW_USTR + o] = acc[mt][nt][2*hh+1] + pb;
                    }
                }
            }
        }
        __syncthreads();

        #pragma unroll
        for (int it = 0; it < 4; it++){
            int t = wid*4 + it;
            float s = 0.f, sq = 0.f;
            #pragma unroll
            for (int k = 0; k < 8; k++){
                float v = us[t*PW_USTR + lane + k*32];
                s += v; sq += v*v;
            }
            #pragma unroll
            for (int off = 16; off; off >>= 1){
                s  += __shfl_xor_sync(0xFFFFFFFFu, s,  off);
                sq += __shfl_xor_sync(0xFFFFFFFFu, sq, off);
            }
            if (lane == 0){
                float mean = s * (1.f/FF);
                smean[t] = mean;
                srstd[t] = rsqrtf(sq * (1.f/FF) - mean*mean + 1e-5f);
            }
        }
        __syncthreads();

        long gbase = ((long)b*TLEN + t0 + p*64) * FF;
        for (int i = tid; i < 64*64; i += 512){
            int t = i >> 6, o4 = i & 63;
            float4 u = *(float4*)&us[t*PW_USTR + o4*4];
            float mean = smean[t], rstd = srstd[t];
            const float4 ga = *(const float4*)&gamma2[o4*4];
            const float4 be = *(const float4*)&beta2[o4*4];
            long idx = gbase + (long)t*FF + o4*4;
            float4 hv = *(const float4*)&src[idx];
            hv.x += gelu_exact((u.x - mean)*rstd*ga.x + be.x);
            hv.y += gelu_exact((u.y - mean)*rstd*ga.y + be.y);
            hv.z += gelu_exact((u.z - mean)*rstd*ga.z + be.z);
            hv.w += gelu_exact((u.w - mean)*rstd*ga.w + be.w);
            *(float4*)&dst[idx] = hv;
            if (last){
                float mv = mask[(long)b*TLEN + t0 + p*64 + t];
                __nv_bfloat162 p0, p1;
                p0.x = __float2bfloat16_rn(hv.x*mv);
                p0.y = __float2bfloat16_rn(hv.y*mv);
                p1.x = __float2bfloat16_rn(hv.z*mv);
                p1.y = __float2bfloat16_rn(hv.w*mv);
                *(__nv_bfloat162*)&g_hhi[idx]   = p0;
                *(__nv_bfloat162*)&g_hhi[idx+2] = p1;
            }
        }
    }
}

// ---------------------------------------------------------------------------
// Kernel 4: 1-term bf16 GEMM (u = W @ h^T), 2-deep pipelined staging over
// 4 k-chunks of 64, fused with the RQ spline. CTA 256 thr / 8 warps.
// ---------------------------------------------------------------------------
__global__ __launch_bounds__(256, 2) void k_proj_mma(const float* __restrict__ x,
                                                     const float* __restrict__ mask,
                                                     const float* __restrict__ proj_b,
                                                     float* __restrict__ out){
    extern __shared__ char smem[];
    uint32_t sb = smem_u32(smem);
    int tid = threadIdx.x, lane = tid & 31, wid = tid >> 5;
    int t0 = blockIdx.x * NT;
    int mtile = blockIdx.y;
    int b = blockIdx.z;
    int m0 = mtile * MT;
    int ch0 = mtile * 4;

    float* smask = (float*)(smem + OFF_MASK);
    if (tid < NT) smask[tid] = mask[(long)b*TLEN + t0 + tid];

    float acc[2][8][4];
    #pragma unroll
    for (int mt = 0; mt < 2; mt++)
        #pragma unroll
        for (int nt = 0; nt < 8; nt++)
            #pragma unroll
            for (int q = 0; q < 4; q++) acc[mt][nt][q] = 0.f;

    int wm = wid & 3, wn = wid >> 2;
    const uint4* srcA = ((const uint4*)g_whi) + (size_t)m0*32;
    const uint4* srcB = ((const uint4*)g_hhi) + ((size_t)b*TLEN + t0)*32;

    #pragma unroll
    for (int s = 0; s < 2; s++){
        uint32_t ab = sb + s*PROJ_STG, bb = ab + 18432;
        for (int i = tid; i < 128*8; i += 256){
            int r = i >> 3, g = i & 7;
            cp16(ab + (uint32_t)(r*PSTR + g*16), srcA + (size_t)r*32 + s*8 + g);
        }
        for (int i = tid; i < 128*8; i += 256){
            int r = i >> 3, g = i & 7;
            cp16(bb + (uint32_t)(r*PSTR + g*16), srcB + (size_t)r*32 + s*8 + g);
        }
        cp_commit();
    }

    uint32_t aoff = (uint32_t)((wm*32 + (lane & 15)) * PSTR + ((lane >> 4) * 8) * 2);
    uint32_t boffc = (uint32_t)((((lane >> 4) * 8) + (lane & 7)) * PSTR
                                + ((lane >> 3) & 1) * 16);

    #pragma unroll
    for (int s = 0; s < 4; s++){
        if (s < 3) cp_waitg1(); else cp_waitg0();
        __syncthreads();
        uint32_t ab = sb + (s & 1)*PROJ_STG, bb = ab + 18432;
        uint32_t aH0 = ab + aoff, aH1 = aH0 + 16*PSTR;
        uint32_t bB[2];
        bB[0] = bb + (uint32_t)((wn*64) * PSTR) + boffc;
        bB[1] = bb + (uint32_t)((wn*64 + 32) * PSTR) + boffc;

        #pragma unroll
        for (int k16 = 0; k16 < 4; k16++){
            uint32_t ko = (uint32_t)(k16 * 32);
            uint32_t Ah[2][4];
            ldm4(Ah[0], aH0 + ko); ldm4(Ah[1], aH1 + ko);
            #pragma unroll
            for (int hf = 0; hf < 2; hf++){
                uint32_t Bh[2][4];
                ldm4(Bh[0], bB[hf] + ko); ldm4(Bh[1], bB[hf] + 16*PSTR + ko);
                #pragma unroll
                for (int mt = 0; mt < 2; mt++){
                    #pragma unroll
                    for (int nt = 0; nt < 4; nt++){
                        uint32_t h0 = Bh[nt>>1][(nt&1)*2], h1 = Bh[nt>>1][(nt&1)*2+1];
                        mma_bf16(acc[mt][hf*4+nt], Ah[mt], h0, h1);
                    }
                }
            }
        }
        __syncthreads();
        if (s < 2){
            int sn = s + 2;
            uint32_t ab2 = sb + (s & 1)*PROJ_STG, bb2 = ab2 + 18432;
            for (int i = tid; i < 128*8; i += 256){
                int r = i >> 3, g = i & 7;
                cp16(ab2 + (uint32_t)(r*PSTR + g*16), srcA + (size_t)r*32 + sn*8 + g);
            }
            for (int i = tid; i < 128*8; i += 256){
                int r = i >> 3, g = i & 7;
                cp16(bb2 + (uint32_t)(r*PSTR + g*16), srcB + (size_t)r*32 + sn*8 + g);
            }
            cp_commit();
        }
    }

    // u -> smem (alias over staging buffers): us[row][t], stride 129 floats
    float* us = (float*)smem;
    #pragma unroll
    for (int mt = 0; mt < 2; mt++){
        #pragma unroll
        for (int g = 0; g < 8; g++){
            int r = wm*32 + mt*16 + (lane >> 2);
            int t = wn*64 + g*8 + (lane & 3)*2;
            #pragma unroll
            for (int hh = 0; hh < 2; hh++){
                int rr = r + hh*8;
                int j = rr & 31;
                int ch = ch0 + (rr >> 5);
                float pb = (j < NJ) ? proj_b[ch*NJ + j] : 0.f;
                us[rr*USTRIDE + t]     = (acc[mt][g][2*hh+0] + pb) * smask[t];
                us[rr*USTRIDE + t + 1] = (acc[mt][g][2*hh+1] + pb) * smask[t+1];
            }
        }
    }
    __syncthreads();

    // --- spline: 4 ch x 128 t = 512 evals, 2 per thread ---
    const float SCALE = 0.0625f;
    int chl = tid >> 6;
    int ch = ch0 + chl;
    float ldsum = 0.f;

    #pragma unroll
    for (int it = 0; it < 2; it++){
        int tl = (tid & 63) + it*64;
        const float* ub = us + (chl*32)*USTRIDE + tl;   // ub[j*USTRIDE]
        float x1v = x[(long)b*CC*TLEN + (long)(HALF + ch)*TLEN + t0 + tl];
        float mv  = smask[tl];

        float uw[10];
        #pragma unroll
        for (int j = 0; j < 10; j++) uw[j] = ub[j*USTRIDE] * SCALE;
        float mx = uw[0];
        #pragma unroll
        for (int j = 1; j < 10; j++) mx = fmaxf(mx, uw[j]);
        float ew[10]; float sw = 0.f;
        #pragma unroll
        for (int j = 0; j < 10; j++){ ew[j] = __expf(uw[j] - mx); sw += ew[j]; }
        float cw[11]; cw[0] = -5.f;
        {
            float inv = __frcp_rn(sw), cs = 0.f;
            #pragma unroll
            for (int j = 0; j < 9; j++){
                cs += fmaf(0.99f, ew[j]*inv, 0.001f);
                cw[j+1] = fmaf(10.f, cs, -5.f);
            }
            cw[10] = 5.f;
        }
        #pragma unroll
        for (int j = 0; j < 10; j++) uw[j] = ub[(10+j)*USTRIDE] * SCALE;
        mx = uw[0];
        #pragma unroll
        for (int j = 1; j < 10; j++) mx = fmaxf(mx, uw[j]);
        sw = 0.f;
        #pragma unroll
        for (int j = 0; j < 10; j++){ ew[j] = __expf(uw[j] - mx); sw += ew[j]; }
        float chh[11]; chh[0] = -5.f;
        {
            float inv = __frcp_rn(sw), cs = 0.f;
            #pragma unroll
            for (int j = 0; j < 9; j++){
                cs += fmaf(0.99f, ew[j]*inv, 0.001f);
                chh[j+1] = fmaf(10.f, cs, -5.f);
            }
            chh[10] = 5.f;
        }

        float xc = fminf(fmaxf(x1v, -5.f), 5.f);
        int idx = 0;
        #pragma unroll
        for (int j = 1; j <= 9; j++) idx += (xc >= cw[j]) ? 1 : 0;

        float cwl = cw[0], cwr = cw[1], chl2 = chh[0], chr = chh[1];
        #pragma unroll
        for (int j = 1; j < 10; j++){
            if (idx == j){ cwl = cw[j]; cwr = cw[j+1]; chl2 = chh[j]; chr = chh[j+1]; }
        }
        float d0 = (idx == 0) ? 1.f : 0.001f + softplus_fast(ub[(19 + idx)*USTRIDE]);
        float d1 = (idx == 9) ? 1.f : 0.001f + softplus_fast(ub[(20 + idx)*USTRIDE]);

        float wb = cwr - cwl, hb = chr - chl2;
        float inv_wb = __frcp_rn(wb);
        float delta = hb * inv_wb;
        float th = (xc - cwl) * inv_wb;
        float omt = 1.f - th;
        float t1m = th * omt;
        float denom = delta + (d0 + d1 - 2.f*delta) * t1m;
        float num = hb * (delta*th*th + d0*t1m);
        float yv = chl2 + num / denom;
        float dnum = delta*delta * (d1*th*th + 2.f*delta*t1m + d0*omt*omt);
        float lad = __logf(dnum) - 2.f*__logf(denom);

        bool inside = (x1v >= -5.f) && (x1v <= 5.f);
        float ov = inside ? yv : x1v;
        ldsum += (inside ? lad : 0.f) * mv;

        out[(long)b*CC*TLEN + (long)(HALF + ch)*TLEN + t0 + tl] = ov * mv;
    }

    // logdet reduction
    #pragma unroll
    for (int off = 16; off; off >>= 1)
        ldsum += __shfl_xor_sync(0xFFFFFFFFu, ldsum, off);
    float* sred = (float*)(smem + OFF_RED);
    if (lane == 0) sred[wid] = ldsum;
    __syncthreads();
    if (tid == 0){
        float s = 0.f;
        #pragma unroll
        for (int k = 0; k < 8; k++) s += sred[k];
        atomicAdd(&out[(long)BB*CC*TLEN + b], s);
    }
}

// ---------------------------------------------------------------------------
extern "C" void kernel_launch(void* const* d_in, const int* in_sizes, int n_in,
                              void* d_out, int out_size){
    const float* x      = (const float*)d_in[0];
    const float* mask   = (const float*)d_in[1];
    const float* pre_w  = (const float*)d_in[2];
    const float* pre_b  = (const float*)d_in[3];
    const float* dw_w   = (const float*)d_in[4];
    const float* dw_b   = (const float*)d_in[5];
    const float* pw_w   = (const float*)d_in[6];
    const float* pw_b   = (const float*)d_in[7];
    const float* gamma1 = (const float*)d_in[8];
    const float* beta1  = (const float*)d_in[9];
    const float* gamma2 = (const float*)d_in[10];
    const float* beta2  = (const float*)d_in[11];
    const float* proj_w = (const float*)d_in[12];
    const float* proj_b = (const float*)d_in[13];
    float* out = (float*)d_out;

    cudaFuncSetAttribute(k_proj_mma, cudaFuncAttributeMaxDynamicSharedMemorySize,
                         PROJ_SMEM_BYTES);
    cudaFuncSetAttribute(k_fused_layer, cudaFuncAttributeMaxDynamicSharedMemorySize,
                         FPW_SMEM_BYTES);
    cudaFuncSetAttribute(k_pre_mma, cudaFuncAttributeMaxDynamicSharedMemorySize,
                         PRE_SMEM_BYTES);

    k_prep_all<<<984, 256>>>(proj_w, pw_w, pre_w);
    k_init<<<dim3(2, HALF, BB), 256>>>(x, mask, out);
    k_pre_mma<<<dim3(TLEN/128, BB), 512, PRE_SMEM_BYTES>>>(x, pre_b);

    int dil = 1;
    for (int i = 0; i < 3; i++){
        k_fused_layer<<<dim3(TLEN/128, BB), 512, FPW_SMEM_BYTES>>>(
            mask,
            dw_w + (long)i*FF*3, dw_b + (long)i*FF,
            gamma1 + (long)i*FF, beta1 + (long)i*FF,
            pw_b + (long)i*FF,
            gamma2 + (long)i*FF, beta2 + (long)i*FF,
            i, dil, (i == 2) ? 1 : 0);
        dil *= 3;
    }

    k_proj_mma<<<dim3(TLEN/NT, MROWS/MT, BB), 256, PROJ_SMEM_BYTES>>>(x, mask, proj_b, out);
}